// round 4
// baseline (speedup 1.0000x reference)
#include <cuda_runtime.h>

// GCN 2-layer forward, fixed shape.
// CSR aggregation, f32x2 GEMM, fused epilogues, 2-stream overlap.
#define N_NODES 100000
#define N_EDGES 3200000
#define F_IN    512
#define HID     16
#define NB      391            // ceil(N_NODES/256)

// ---------------- device scratch (no allocations allowed) ----------------
__device__ int   g_is64;
__device__ int   g_deg   [NB * 256];      // edge-target histogram
__device__ int   g_off   [N_NODES + 1];   // CSR offsets
__device__ int   g_cursor[N_NODES];
__device__ int   g_csr   [N_EDGES];       // row ids sorted by col
__device__ float g_dinv  [N_NODES];
__device__ float g_p     [N_NODES * HID]; // layer-1 features (scaled after k_scale)
__device__ float g_p2    [N_NODES * HID]; // layer-2 pre-scaled features

// ---------------- init: zero histogram + detect edge dtype ----------------
__global__ void k_init(const int* __restrict__ e) {
    int i = blockIdx.x * blockDim.x + threadIdx.x;
    g_deg[i] = 0;
    if (blockIdx.x == 0) {
        // int64 little-endian values < 2^31 -> odd words all zero
        int odd = e[2 * threadIdx.x + 1];
        int any = __syncthreads_or(odd != 0);
        if (threadIdx.x == 0) g_is64 = !any;
    }
}

// ---------------- histogram ----------------------------------------------
__global__ void k_hist(const int* __restrict__ e) {
    int i = blockIdx.x * blockDim.x + threadIdx.x;
    if (i >= N_EDGES) return;
    int c;
    if (g_is64) c = (int)((const long long*)e)[(long long)N_EDGES + i];
    else        c = e[N_EDGES + i];
    atomicAdd(&g_deg[c], 1);
}

// ---------------- single-block scan: offsets + cursor + dinv --------------
#define SCAN_T 1024
#define SEG    98              // ceil(N_NODES / SCAN_T)
__global__ __launch_bounds__(SCAN_T) void k_scan() {
    __shared__ int wtot[32];
    __shared__ int wexc[32];
    __shared__ int s_total;
    int t = threadIdx.x;
    int lo = t * SEG;
    int hi = lo + SEG; if (hi > N_NODES) hi = N_NODES;

    int sum = 0;
    for (int i = lo; i < hi; i++) sum += g_deg[i];

    int lane = t & 31, wid = t >> 5;
    int v = sum;
#pragma unroll
    for (int d = 1; d < 32; d <<= 1) {
        int u = __shfl_up_sync(0xffffffffu, v, d);
        if (lane >= d) v += u;
    }
    if (lane == 31) wtot[wid] = v;
    __syncthreads();
    if (wid == 0) {
        int w = wtot[lane];
        int vv = w;
#pragma unroll
        for (int d = 1; d < 32; d <<= 1) {
            int u = __shfl_up_sync(0xffffffffu, vv, d);
            if (lane >= d) vv += u;
        }
        wexc[lane] = vv - w;
        if (lane == 31) s_total = vv;
    }
    __syncthreads();

    int acc = (v - sum) + wexc[wid];
    for (int i = lo; i < hi; i++) {
        int dg = g_deg[i];
        g_off[i] = acc;
        g_cursor[i] = acc;
        g_dinv[i] = rsqrtf((float)(dg + 1));   // +1 self-loop
        acc += dg;
    }
    if (t == 0) g_off[N_NODES] = s_total;
}

// ---------------- CSR bucket fill ----------------------------------------
__global__ void k_build(const int* __restrict__ e) {
    int i = blockIdx.x * blockDim.x + threadIdx.x;
    if (i >= N_EDGES) return;
    int r, c;
    if (g_is64) {
        r = (int)((const long long*)e)[i];
        c = (int)((const long long*)e)[(long long)N_EDGES + i];
    } else {
        r = e[i];
        c = e[N_EDGES + i];
    }
    int pos = atomicAdd(&g_cursor[c], 1);
    g_csr[pos] = r;
}

// ---------------- GEMM1: p = x @ W1 (unscaled), f32x2 FMA ----------------
__device__ __forceinline__ void ffma2(unsigned long long& acc,
                                      unsigned long long a,
                                      unsigned long long b) {
    asm("fma.rn.f32x2 %0, %1, %2, %0;" : "+l"(acc) : "l"(a), "l"(b));
}

__device__ __forceinline__ unsigned long long bcast2(float x) {
    unsigned long long r;
    asm("mov.b64 %0, {%1, %1};" : "=l"(r) : "f"(x));
    return r;
}

__global__ __launch_bounds__(256) void k_gemm1(const float* __restrict__ x,
                                               const float* __restrict__ W1) {
    __shared__ float sW[F_IN * HID];   // 32 KB
    for (int i = threadIdx.x; i < (F_IN * HID) / 4; i += blockDim.x)
        ((float4*)sW)[i] = ((const float4*)W1)[i];
    __syncthreads();

    int t = blockIdx.x * blockDim.x + threadIdx.x;
    size_t r0 = (size_t)t * 2;
    if (r0 >= N_NODES) return;

    unsigned long long acc[2][8];
#pragma unroll
    for (int m = 0; m < 2; m++)
#pragma unroll
        for (int j = 0; j < 8; j++) acc[m][j] = 0ull;

    const float* xb = x + r0 * F_IN;

    for (int k = 0; k < F_IN; k += 4) {
        float4 xv0 = __ldg((const float4*)(xb + k));
        float4 xv1 = __ldg((const float4*)(xb + F_IN + k));
#pragma unroll
        for (int kk = 0; kk < 4; kk++) {
            const unsigned long long* wp =
                (const unsigned long long*)(sW + (k + kk) * 16);
            unsigned long long w0 = wp[0], w1 = wp[1], w2 = wp[2], w3 = wp[3];
            unsigned long long w4 = wp[4], w5 = wp[5], w6 = wp[6], w7 = wp[7];
            float xs0 = (kk == 0) ? xv0.x : (kk == 1) ? xv0.y : (kk == 2) ? xv0.z : xv0.w;
            float xs1 = (kk == 0) ? xv1.x : (kk == 1) ? xv1.y : (kk == 2) ? xv1.z : xv1.w;
            unsigned long long xp0 = bcast2(xs0);
            unsigned long long xp1 = bcast2(xs1);
            ffma2(acc[0][0], xp0, w0); ffma2(acc[0][1], xp0, w1);
            ffma2(acc[0][2], xp0, w2); ffma2(acc[0][3], xp0, w3);
            ffma2(acc[0][4], xp0, w4); ffma2(acc[0][5], xp0, w5);
            ffma2(acc[0][6], xp0, w6); ffma2(acc[0][7], xp0, w7);
            ffma2(acc[1][0], xp1, w0); ffma2(acc[1][1], xp1, w1);
            ffma2(acc[1][2], xp1, w2); ffma2(acc[1][3], xp1, w3);
            ffma2(acc[1][4], xp1, w4); ffma2(acc[1][5], xp1, w5);
            ffma2(acc[1][6], xp1, w6); ffma2(acc[1][7], xp1, w7);
        }
    }

#pragma unroll
    for (int m = 0; m < 2; m++) {
        if (r0 + m >= N_NODES) break;
        float* dst = g_p + (r0 + m) * HID;
#pragma unroll
        for (int j = 0; j < 8; j++) {
            float lo, hi;
            asm("mov.b64 {%0, %1}, %2;" : "=f"(lo), "=f"(hi) : "l"(acc[m][j]));
            dst[2 * j]     = lo;
            dst[2 * j + 1] = hi;
        }
    }
}

// ---------------- scale: p[i] *= dinv[i] (overlaps k_build) ----------------
__global__ void k_scale() {
    int t = blockIdx.x * blockDim.x + threadIdx.x;   // one float4 per thread
    if (t >= N_NODES * 4) return;
    int node = t >> 2;
    float d = g_dinv[node];
    float4 v = ((float4*)g_p)[t];
    v.x *= d; v.y *= d; v.z *= d; v.w *= d;
    ((float4*)g_p)[t] = v;
}

// ---------------- fused agg1 + relu + layer-2 linear ----------------------
// 4 threads per node (quads within warp). Gather agg quad, build t = relu(...),
// exchange quads via shfl_xor to run the 16x16 GEMM, write p2 = o*dinv.
__global__ __launch_bounds__(256) void k_agg_l2(const float* __restrict__ b1,
                                                const float* __restrict__ W2) {
    __shared__ float sW2[HID * 16];
    if (threadIdx.x < 64)
        ((float4*)sW2)[threadIdx.x] = ((const float4*)W2)[threadIdx.x];
    __syncthreads();

    int t = blockIdx.x * blockDim.x + threadIdx.x;
    int node = t >> 2;
    int q    = t & 3;
    bool valid = node < N_NODES;

    int e = 0, end = 0;
    if (valid) { e = g_off[node]; end = g_off[node + 1]; }

    float4 a0 = make_float4(0.f, 0.f, 0.f, 0.f);
    float4 a1 = make_float4(0.f, 0.f, 0.f, 0.f);
    for (; e + 2 <= end; e += 2) {
        int r0 = __ldg(&g_csr[e]);
        int r1 = __ldg(&g_csr[e + 1]);
        float4 v0 = __ldg((const float4*)(g_p + (size_t)r0 * HID + q * 4));
        float4 v1 = __ldg((const float4*)(g_p + (size_t)r1 * HID + q * 4));
        a0.x += v0.x; a0.y += v0.y; a0.z += v0.z; a0.w += v0.w;
        a1.x += v1.x; a1.y += v1.y; a1.z += v1.z; a1.w += v1.w;
    }
    if (e < end) {
        int r0 = __ldg(&g_csr[e]);
        float4 v0 = __ldg((const float4*)(g_p + (size_t)r0 * HID + q * 4));
        a0.x += v0.x; a0.y += v0.y; a0.z += v0.z; a0.w += v0.w;
    }

    float d = valid ? g_dinv[node] : 0.f;
    float4 ps = valid ? ((const float4*)(g_p + (size_t)node * HID))[q]
                      : make_float4(0.f, 0.f, 0.f, 0.f);
    float4 bq = __ldg((const float4*)b1 + q);

    float tq[4];
    tq[0] = fmaxf((a0.x + a1.x + ps.x) * d + bq.x, 0.f);
    tq[1] = fmaxf((a0.y + a1.y + ps.y) * d + bq.y, 0.f);
    tq[2] = fmaxf((a0.z + a1.z + ps.z) * d + bq.z, 0.f);
    tq[3] = fmaxf((a0.w + a1.w + ps.w) * d + bq.w, 0.f);

    // 16x16 GEMM across the quad: j = 4*(q^r)+k
    float o[4] = {0.f, 0.f, 0.f, 0.f};
#pragma unroll
    for (int r = 0; r < 4; r++) {
        float tv0 = __shfl_xor_sync(0xffffffffu, tq[0], r);
        float tv1 = __shfl_xor_sync(0xffffffffu, tq[1], r);
        float tv2 = __shfl_xor_sync(0xffffffffu, tq[2], r);
        float tv3 = __shfl_xor_sync(0xffffffffu, tq[3], r);
        int g = (q ^ r) * 4;
        const float* w0 = sW2 + (g + 0) * 16 + q * 4;
        const float* w1 = sW2 + (g + 1) * 16 + q * 4;
        const float* w2 = sW2 + (g + 2) * 16 + q * 4;
        const float* w3 = sW2 + (g + 3) * 16 + q * 4;
#pragma unroll
        for (int c = 0; c < 4; c++)
            o[c] += tv0 * w0[c] + tv1 * w1[c] + tv2 * w2[c] + tv3 * w3[c];
    }

    if (valid) {
        float4 v;
        v.x = o[0] * d; v.y = o[1] * d; v.z = o[2] * d; v.w = o[3] * d;
        ((float4*)(g_p2 + (size_t)node * HID))[q] = v;
    }
}

// ---------------- fused agg2 + bias + log_softmax -------------------------
__global__ __launch_bounds__(256) void k_agg_final(const float* __restrict__ b2,
                                                   float* __restrict__ out) {
    int t = blockIdx.x * blockDim.x + threadIdx.x;
    int node = t >> 2;
    int q    = t & 3;
    bool valid = node < N_NODES;

    int e = 0, end = 0;
    if (valid) { e = g_off[node]; end = g_off[node + 1]; }

    float4 a0 = make_float4(0.f, 0.f, 0.f, 0.f);
    float4 a1 = make_float4(0.f, 0.f, 0.f, 0.f);
    for (; e + 2 <= end; e += 2) {
        int r0 = __ldg(&g_csr[e]);
        int r1 = __ldg(&g_csr[e + 1]);
        float4 v0 = __ldg((const float4*)(g_p2 + (size_t)r0 * HID + q * 4));
        float4 v1 = __ldg((const float4*)(g_p2 + (size_t)r1 * HID + q * 4));
        a0.x += v0.x; a0.y += v0.y; a0.z += v0.z; a0.w += v0.w;
        a1.x += v1.x; a1.y += v1.y; a1.z += v1.z; a1.w += v1.w;
    }
    if (e < end) {
        int r0 = __ldg(&g_csr[e]);
        float4 v0 = __ldg((const float4*)(g_p2 + (size_t)r0 * HID + q * 4));
        a0.x += v0.x; a0.y += v0.y; a0.z += v0.z; a0.w += v0.w;
    }

    float d = valid ? g_dinv[node] : 0.f;
    float4 ps = valid ? ((const float4*)(g_p2 + (size_t)node * HID))[q]
                      : make_float4(0.f, 0.f, 0.f, 0.f);
    float4 bq = __ldg((const float4*)b2 + q);

    float l[4];
    l[0] = (a0.x + a1.x + ps.x) * d + bq.x;
    l[1] = (a0.y + a1.y + ps.y) * d + bq.y;
    l[2] = (a0.z + a1.z + ps.z) * d + bq.z;
    l[3] = (a0.w + a1.w + ps.w) * d + bq.w;

    // log-softmax across the quad
    float m = fmaxf(fmaxf(l[0], l[1]), fmaxf(l[2], l[3]));
    m = fmaxf(m, __shfl_xor_sync(0xffffffffu, m, 1));
    m = fmaxf(m, __shfl_xor_sync(0xffffffffu, m, 2));
    float s = expf(l[0] - m) + expf(l[1] - m) + expf(l[2] - m) + expf(l[3] - m);
    s += __shfl_xor_sync(0xffffffffu, s, 1);
    s += __shfl_xor_sync(0xffffffffu, s, 2);
    float lse = m + logf(s);

    if (valid) {
        float4 v;
        v.x = l[0] - lse; v.y = l[1] - lse; v.z = l[2] - lse; v.w = l[3] - lse;
        ((float4*)(out + (size_t)node * HID))[q] = v;
    }
}

// ---------------- host orchestration -------------------------------------
// main:  init -> hist -> scan -> build -> [join] -> agg_l2 -> agg_final
// side:  gemm1 -> (wait scan) -> scale
extern "C" void kernel_launch(void* const* d_in, const int* in_sizes, int n_in,
                              void* d_out, int out_size) {
    const float* x  = (const float*)d_in[0];
    const int*   ei = (const int*)d_in[1];
    const float* W1 = (const float*)d_in[2];
    const float* b1 = (const float*)d_in[3];
    const float* W2 = (const float*)d_in[4];
    const float* b2 = (const float*)d_in[5];
    float* out = (float*)d_out;

    const int TB = 256;
    int grid_edges = (N_EDGES + TB - 1) / TB;
    int grid_gemm  = ((N_NODES + 1) / 2 + TB - 1) / TB;
    int grid_agg   = (N_NODES * 4 + TB - 1) / TB;

    cudaStream_t s2;
    cudaEvent_t evFork, evScan, evScale;
    cudaStreamCreateWithFlags(&s2, cudaStreamNonBlocking);
    cudaEventCreateWithFlags(&evFork, cudaEventDisableTiming);
    cudaEventCreateWithFlags(&evScan, cudaEventDisableTiming);
    cudaEventCreateWithFlags(&evScale, cudaEventDisableTiming);

    // fork
    cudaEventRecord(evFork, 0);
    cudaStreamWaitEvent(s2, evFork, 0);
    k_gemm1<<<grid_gemm, TB, 0, s2>>>(x, W1);

    // main: edge pipeline
    k_init <<<NB, TB>>>(ei);
    k_hist <<<grid_edges, TB>>>(ei);
    k_scan <<<1, SCAN_T>>>();
    cudaEventRecord(evScan, 0);
    k_build<<<grid_edges, TB>>>(ei);

    // side: scale after gemm1 + scan (overlaps build)
    cudaStreamWaitEvent(s2, evScan, 0);
    k_scale<<<(N_NODES * 4 + TB - 1) / TB, TB, 0, s2>>>();
    cudaEventRecord(evScale, s2);

    // join
    cudaStreamWaitEvent(0, evScale, 0);
    k_agg_l2   <<<grid_agg, TB>>>(b1, W2);
    k_agg_final<<<grid_agg, TB>>>(b2, out);

    cudaStreamDestroy(s2);
    cudaEventDestroy(evFork);
    cudaEventDestroy(evScan);
    cudaEventDestroy(evScale);
}

// round 5
// speedup vs baseline: 2.1319x; 2.1319x over previous
#include <cuda_runtime.h>

// GCN 2-layer forward, fixed shape.
// CSR aggregation, f32x2 GEMM, fused epilogues, 2-stream overlap.
#define N_NODES 100000
#define N_EDGES 3200000
#define F_IN    512
#define HID     16
#define NB      391            // ceil(N_NODES/256)

// ---------------- device scratch (no allocations allowed) ----------------
__device__ int   g_is64;
__device__ int   g_deg   [NB * 256];      // edge-target histogram
__device__ int   g_bsum  [NB];
__device__ int   g_boff  [NB];
__device__ int   g_off   [N_NODES + 1];   // CSR offsets
__device__ int   g_cursor[N_NODES];
__device__ int   g_csr   [N_EDGES];       // row ids sorted by col
__device__ float g_dinv  [N_NODES];
__device__ float g_p     [N_NODES * HID]; // layer-1 features
__device__ float g_p2    [N_NODES * HID]; // layer-2 pre-scaled features

// ---------------- init: zero histogram + detect edge dtype ----------------
__global__ void k_init(const int* __restrict__ e) {
    int i = blockIdx.x * blockDim.x + threadIdx.x;
    g_deg[i] = 0;
    if (blockIdx.x == 0) {
        // int64 little-endian values < 2^31 -> odd words all zero
        int odd = e[2 * threadIdx.x + 1];
        int any = __syncthreads_or(odd != 0);
        if (threadIdx.x == 0) g_is64 = !any;
    }
}

// ---------------- histogram ----------------------------------------------
__global__ void k_hist(const int* __restrict__ e) {
    int i = blockIdx.x * blockDim.x + threadIdx.x;
    if (i >= N_EDGES) return;
    int c;
    if (g_is64) c = (int)((const long long*)e)[(long long)N_EDGES + i];
    else        c = e[N_EDGES + i];
    atomicAdd(&g_deg[c], 1);
}

// ---------------- grid-wide 3-kernel scan ---------------------------------
__global__ void k_partial() {
    __shared__ int s[256];
    int i = blockIdx.x * 256 + threadIdx.x;
    s[threadIdx.x] = g_deg[i];
    __syncthreads();
    for (int d = 128; d > 0; d >>= 1) {
        if (threadIdx.x < d) s[threadIdx.x] += s[threadIdx.x + d];
        __syncthreads();
    }
    if (threadIdx.x == 0) g_bsum[blockIdx.x] = s[0];
}

__global__ __launch_bounds__(512) void k_scanb() {
    // single-block exclusive scan over NB (<=512) block sums
    __shared__ int s[512];
    int t = threadIdx.x;
    int v = (t < NB) ? g_bsum[t] : 0;
    s[t] = v;
    __syncthreads();
    for (int d = 1; d < 512; d <<= 1) {
        int u = (t >= d) ? s[t - d] : 0;
        __syncthreads();
        s[t] += u;
        __syncthreads();
    }
    if (t < NB) g_boff[t] = s[t] - v;          // exclusive
    if (t == 0) g_off[N_NODES] = s[511];       // == N_EDGES (pad sums are 0)
}

__global__ void k_off() {
    __shared__ int s[256];
    int i = blockIdx.x * 256 + threadIdx.x;
    int v = g_deg[i];
    s[threadIdx.x] = v;
    __syncthreads();
    for (int d = 1; d < 256; d <<= 1) {
        int t = (threadIdx.x >= d) ? s[threadIdx.x - d] : 0;
        __syncthreads();
        s[threadIdx.x] += t;
        __syncthreads();
    }
    int excl = s[threadIdx.x] - v + g_boff[blockIdx.x];
    if (i < N_NODES) {
        g_off[i] = excl;
        g_cursor[i] = excl;
        g_dinv[i] = rsqrtf((float)(v + 1));   // +1 self-loop (fused dinv)
    }
}

// ---------------- CSR bucket fill ----------------------------------------
__global__ void k_build(const int* __restrict__ e) {
    int i = blockIdx.x * blockDim.x + threadIdx.x;
    if (i >= N_EDGES) return;
    int r, c;
    if (g_is64) {
        r = (int)((const long long*)e)[i];
        c = (int)((const long long*)e)[(long long)N_EDGES + i];
    } else {
        r = e[i];
        c = e[N_EDGES + i];
    }
    int pos = atomicAdd(&g_cursor[c], 1);
    g_csr[pos] = r;
}

// ---------------- GEMM1: p = x @ W1 (unscaled), f32x2 FMA ----------------
__device__ __forceinline__ void ffma2(unsigned long long& acc,
                                      unsigned long long a,
                                      unsigned long long b) {
    asm("fma.rn.f32x2 %0, %1, %2, %0;" : "+l"(acc) : "l"(a), "l"(b));
}

__device__ __forceinline__ unsigned long long bcast2(float x) {
    unsigned long long r;
    asm("mov.b64 %0, {%1, %1};" : "=l"(r) : "f"(x));
    return r;
}

__global__ __launch_bounds__(256) void k_gemm1(const float* __restrict__ x,
                                               const float* __restrict__ W1) {
    __shared__ float sW[F_IN * HID];   // 32 KB
    for (int i = threadIdx.x; i < (F_IN * HID) / 4; i += blockDim.x)
        ((float4*)sW)[i] = ((const float4*)W1)[i];
    __syncthreads();

    int t = blockIdx.x * blockDim.x + threadIdx.x;
    size_t r0 = (size_t)t * 2;
    if (r0 >= N_NODES) return;

    unsigned long long acc[2][8];
#pragma unroll
    for (int m = 0; m < 2; m++)
#pragma unroll
        for (int j = 0; j < 8; j++) acc[m][j] = 0ull;

    const float* xb = x + r0 * F_IN;

    for (int k = 0; k < F_IN; k += 4) {
        float4 xv0 = __ldg((const float4*)(xb + k));
        float4 xv1 = __ldg((const float4*)(xb + F_IN + k));
#pragma unroll
        for (int kk = 0; kk < 4; kk++) {
            const unsigned long long* wp =
                (const unsigned long long*)(sW + (k + kk) * 16);
            unsigned long long w0 = wp[0], w1 = wp[1], w2 = wp[2], w3 = wp[3];
            unsigned long long w4 = wp[4], w5 = wp[5], w6 = wp[6], w7 = wp[7];
            float xs0 = (kk == 0) ? xv0.x : (kk == 1) ? xv0.y : (kk == 2) ? xv0.z : xv0.w;
            float xs1 = (kk == 0) ? xv1.x : (kk == 1) ? xv1.y : (kk == 2) ? xv1.z : xv1.w;
            unsigned long long xp0 = bcast2(xs0);
            unsigned long long xp1 = bcast2(xs1);
            ffma2(acc[0][0], xp0, w0); ffma2(acc[0][1], xp0, w1);
            ffma2(acc[0][2], xp0, w2); ffma2(acc[0][3], xp0, w3);
            ffma2(acc[0][4], xp0, w4); ffma2(acc[0][5], xp0, w5);
            ffma2(acc[0][6], xp0, w6); ffma2(acc[0][7], xp0, w7);
            ffma2(acc[1][0], xp1, w0); ffma2(acc[1][1], xp1, w1);
            ffma2(acc[1][2], xp1, w2); ffma2(acc[1][3], xp1, w3);
            ffma2(acc[1][4], xp1, w4); ffma2(acc[1][5], xp1, w5);
            ffma2(acc[1][6], xp1, w6); ffma2(acc[1][7], xp1, w7);
        }
    }

#pragma unroll
    for (int m = 0; m < 2; m++) {
        if (r0 + m >= N_NODES) break;
        float* dst = g_p + (r0 + m) * HID;
#pragma unroll
        for (int j = 0; j < 8; j++) {
            float lo, hi;
            asm("mov.b64 {%0, %1}, %2;" : "=f"(lo), "=f"(hi) : "l"(acc[m][j]));
            dst[2 * j]     = lo;
            dst[2 * j + 1] = hi;
        }
    }
}

// ---------------- scale: p[i] *= dinv[i] (overlaps k_build) ----------------
__global__ void k_scale() {
    int t = blockIdx.x * blockDim.x + threadIdx.x;   // one float4 per thread
    if (t >= N_NODES * 4) return;
    int node = t >> 2;
    float d = g_dinv[node];
    float4 v = ((float4*)g_p)[t];
    v.x *= d; v.y *= d; v.z *= d; v.w *= d;
    ((float4*)g_p)[t] = v;
}

// ---------------- fused agg1 + relu + layer-2 linear ----------------------
__global__ __launch_bounds__(256) void k_agg_l2(const float* __restrict__ b1,
                                                const float* __restrict__ W2) {
    __shared__ float sW2[HID * 16];
    if (threadIdx.x < 64)
        ((float4*)sW2)[threadIdx.x] = ((const float4*)W2)[threadIdx.x];
    __syncthreads();

    int t = blockIdx.x * blockDim.x + threadIdx.x;
    int node = t >> 2;
    int q    = t & 3;
    bool valid = node < N_NODES;

    int e = 0, end = 0;
    if (valid) { e = g_off[node]; end = g_off[node + 1]; }

    float4 a0 = make_float4(0.f, 0.f, 0.f, 0.f);
    float4 a1 = make_float4(0.f, 0.f, 0.f, 0.f);
    for (; e + 2 <= end; e += 2) {
        int r0 = __ldg(&g_csr[e]);
        int r1 = __ldg(&g_csr[e + 1]);
        float4 v0 = __ldg((const float4*)(g_p + (size_t)r0 * HID + q * 4));
        float4 v1 = __ldg((const float4*)(g_p + (size_t)r1 * HID + q * 4));
        a0.x += v0.x; a0.y += v0.y; a0.z += v0.z; a0.w += v0.w;
        a1.x += v1.x; a1.y += v1.y; a1.z += v1.z; a1.w += v1.w;
    }
    if (e < end) {
        int r0 = __ldg(&g_csr[e]);
        float4 v0 = __ldg((const float4*)(g_p + (size_t)r0 * HID + q * 4));
        a0.x += v0.x; a0.y += v0.y; a0.z += v0.z; a0.w += v0.w;
    }

    float d = valid ? g_dinv[node] : 0.f;
    float4 ps = valid ? ((const float4*)(g_p + (size_t)node * HID))[q]
                      : make_float4(0.f, 0.f, 0.f, 0.f);
    float4 bq = __ldg((const float4*)b1 + q);

    float tq[4];
    tq[0] = fmaxf((a0.x + a1.x + ps.x) * d + bq.x, 0.f);
    tq[1] = fmaxf((a0.y + a1.y + ps.y) * d + bq.y, 0.f);
    tq[2] = fmaxf((a0.z + a1.z + ps.z) * d + bq.z, 0.f);
    tq[3] = fmaxf((a0.w + a1.w + ps.w) * d + bq.w, 0.f);

    // 16x16 GEMM across the quad: rows j = 4*(q^r)+k
    float o[4] = {0.f, 0.f, 0.f, 0.f};
#pragma unroll
    for (int r = 0; r < 4; r++) {
        float tv0 = __shfl_xor_sync(0xffffffffu, tq[0], r);
        float tv1 = __shfl_xor_sync(0xffffffffu, tq[1], r);
        float tv2 = __shfl_xor_sync(0xffffffffu, tq[2], r);
        float tv3 = __shfl_xor_sync(0xffffffffu, tq[3], r);
        int g = (q ^ r) * 4;
        const float* w0 = sW2 + (g + 0) * 16 + q * 4;
        const float* w1 = sW2 + (g + 1) * 16 + q * 4;
        const float* w2 = sW2 + (g + 2) * 16 + q * 4;
        const float* w3 = sW2 + (g + 3) * 16 + q * 4;
#pragma unroll
        for (int c = 0; c < 4; c++)
            o[c] += tv0 * w0[c] + tv1 * w1[c] + tv2 * w2[c] + tv3 * w3[c];
    }

    if (valid) {
        float4 v;
        v.x = o[0] * d; v.y = o[1] * d; v.z = o[2] * d; v.w = o[3] * d;
        ((float4*)(g_p2 + (size_t)node * HID))[q] = v;
    }
}

// ---------------- fused agg2 + bias + log_softmax -------------------------
__global__ __launch_bounds__(256) void k_agg_final(const float* __restrict__ b2,
                                                   float* __restrict__ out) {
    int t = blockIdx.x * blockDim.x + threadIdx.x;
    int node = t >> 2;
    int q    = t & 3;
    bool valid = node < N_NODES;

    int e = 0, end = 0;
    if (valid) { e = g_off[node]; end = g_off[node + 1]; }

    float4 a0 = make_float4(0.f, 0.f, 0.f, 0.f);
    float4 a1 = make_float4(0.f, 0.f, 0.f, 0.f);
    for (; e + 2 <= end; e += 2) {
        int r0 = __ldg(&g_csr[e]);
        int r1 = __ldg(&g_csr[e + 1]);
        float4 v0 = __ldg((const float4*)(g_p2 + (size_t)r0 * HID + q * 4));
        float4 v1 = __ldg((const float4*)(g_p2 + (size_t)r1 * HID + q * 4));
        a0.x += v0.x; a0.y += v0.y; a0.z += v0.z; a0.w += v0.w;
        a1.x += v1.x; a1.y += v1.y; a1.z += v1.z; a1.w += v1.w;
    }
    if (e < end) {
        int r0 = __ldg(&g_csr[e]);
        float4 v0 = __ldg((const float4*)(g_p2 + (size_t)r0 * HID + q * 4));
        a0.x += v0.x; a0.y += v0.y; a0.z += v0.z; a0.w += v0.w;
    }

    float d = valid ? g_dinv[node] : 0.f;
    float4 ps = valid ? ((const float4*)(g_p2 + (size_t)node * HID))[q]
                      : make_float4(0.f, 0.f, 0.f, 0.f);
    float4 bq = __ldg((const float4*)b2 + q);

    float l[4];
    l[0] = (a0.x + a1.x + ps.x) * d + bq.x;
    l[1] = (a0.y + a1.y + ps.y) * d + bq.y;
    l[2] = (a0.z + a1.z + ps.z) * d + bq.z;
    l[3] = (a0.w + a1.w + ps.w) * d + bq.w;

    // log-softmax across the quad
    float m = fmaxf(fmaxf(l[0], l[1]), fmaxf(l[2], l[3]));
    m = fmaxf(m, __shfl_xor_sync(0xffffffffu, m, 1));
    m = fmaxf(m, __shfl_xor_sync(0xffffffffu, m, 2));
    float s = expf(l[0] - m) + expf(l[1] - m) + expf(l[2] - m) + expf(l[3] - m);
    s += __shfl_xor_sync(0xffffffffu, s, 1);
    s += __shfl_xor_sync(0xffffffffu, s, 2);
    float lse = m + logf(s);

    if (valid) {
        float4 v;
        v.x = l[0] - lse; v.y = l[1] - lse; v.z = l[2] - lse; v.w = l[3] - lse;
        ((float4*)(out + (size_t)node * HID))[q] = v;
    }
}

// ---------------- host orchestration -------------------------------------
// main:  init -> hist -> partial -> scanb -> off -> build -> [join] -> agg_l2 -> agg_final
// side:  gemm1 -> (wait off) -> scale
extern "C" void kernel_launch(void* const* d_in, const int* in_sizes, int n_in,
                              void* d_out, int out_size) {
    const float* x  = (const float*)d_in[0];
    const int*   ei = (const int*)d_in[1];
    const float* W1 = (const float*)d_in[2];
    const float* b1 = (const float*)d_in[3];
    const float* W2 = (const float*)d_in[4];
    const float* b2 = (const float*)d_in[5];
    float* out = (float*)d_out;

    const int TB = 256;
    int grid_edges = (N_EDGES + TB - 1) / TB;
    int grid_gemm  = ((N_NODES + 1) / 2 + TB - 1) / TB;
    int grid_agg   = (N_NODES * 4 + TB - 1) / TB;

    cudaStream_t s2;
    cudaEvent_t evFork, evScan, evScale;
    cudaStreamCreateWithFlags(&s2, cudaStreamNonBlocking);
    cudaEventCreateWithFlags(&evFork, cudaEventDisableTiming);
    cudaEventCreateWithFlags(&evScan, cudaEventDisableTiming);
    cudaEventCreateWithFlags(&evScale, cudaEventDisableTiming);

    // fork
    cudaEventRecord(evFork, 0);
    cudaStreamWaitEvent(s2, evFork, 0);
    k_gemm1<<<grid_gemm, TB, 0, s2>>>(x, W1);

    // main: edge pipeline
    k_init   <<<NB, TB>>>(ei);
    k_hist   <<<grid_edges, TB>>>(ei);
    k_partial<<<NB, TB>>>();
    k_scanb  <<<1, 512>>>();
    k_off    <<<NB, TB>>>();
    cudaEventRecord(evScan, 0);
    k_build  <<<grid_edges, TB>>>(ei);

    // side: scale after gemm1 + offsets (overlaps build)
    cudaStreamWaitEvent(s2, evScan, 0);
    k_scale<<<(N_NODES * 4 + TB - 1) / TB, TB, 0, s2>>>();
    cudaEventRecord(evScale, s2);

    // join
    cudaStreamWaitEvent(0, evScale, 0);
    k_agg_l2   <<<grid_agg, TB>>>(b1, W2);
    k_agg_final<<<grid_agg, TB>>>(b2, out);

    cudaStreamDestroy(s2);
    cudaEventDestroy(evFork);
    cudaEventDestroy(evScan);
    cudaEventDestroy(evScale);
}